// round 7
// baseline (speedup 1.0000x reference)
#include <cuda_runtime.h>
#include <cuda_fp16.h>

// VectorQuantizer: z [32,4096,64] fp32, W [512,64] fp32.
// Out fp32: z_q_st (8388608) | indices-as-float (131072) | loss (1).
//
// R7: single fused kernel (prep + filter + rescore + epilogue + loss).
// fp16 mma filter w/ running-min threshold (proven superset; rel_err 0.0 in
// R4-R6), ballot-aggregated candidate recording, deferred exact rescore with
// the bitwise reference chain, fixed-point deterministic global loss with
// last-CTA finalize (graph-replay safe: accumulators self-reset).

#define DIM       64
#define KCODES    512
#define NROWS     131072
#define ROWS_CTA  256
#define GRIDM     (NROWS / ROWS_CTA)     // 512
#define THREADS   512
#define NELEM_ZQ  (NROWS * DIM)
#define SZ_STRIDE 66                     // fp32 row stride in smem (words)
#define SW_STRIDE 36                     // fp16-pair row stride (words)
#define CAP       8192                   // candidate entries

typedef unsigned int u32;
typedef unsigned long long u64;

__device__ u64 g_acc  = 0ull;            // fixed-point loss accumulator
__device__ u32 g_done = 0u;              // CTA completion counter

__device__ __forceinline__ u32 fflip(float x) {
    u32 u = __float_as_uint(x);
    return (u & 0x80000000u) ? ~u : (u | 0x80000000u);
}

__global__ __launch_bounds__(THREADS, 1)
void vq_all(const float* __restrict__ z, const float* __restrict__ W,
            float* __restrict__ out, int out_size) {
    extern __shared__ char smraw[];
    u64*    sbest = (u64*)smraw;                                   // 256*8
    double* sred  = (double*)(smraw + 2048);                       // 512*8
    float*  sz    = (float*)(smraw + 6144);                        // 256*66*4
    u32*    sW    = (u32*)(smraw + 6144 + ROWS_CTA * SZ_STRIDE * 4);
    float*  swsq  = (float*)((char*)sW + KCODES * SW_STRIDE * 4);  // 512*4
    float*  szz   = swsq + KCODES;                                 // 256*4
    float*  swid  = szz + ROWS_CTA;                                // 256*4
    u32*    scand = (u32*)(swid + ROWS_CTA);                       // CAP*4
    u32*    sctl  = scand + CAP;                                   // cnt, ovf

    const int tid  = threadIdx.x;
    const int lane = tid & 31;
    const int wid  = tid >> 5;
    const int gid  = lane >> 2;
    const int tig  = lane & 3;
    const int rowbase = blockIdx.x * ROWS_CTA;
    const u32 FULL = 0xFFFFFFFFu;

    // ===== Phase 1: wsq via two coalesced 256-row chunks through sz =====
    #pragma unroll 1
    for (int c = 0; c < 2; c++) {
        const float2* Wg = (const float2*)(W + (size_t)c * 256 * DIM);
        for (int i = tid; i < 256 * (DIM / 2); i += THREADS) {
            int r = i >> 5, kw = i & 31;
            *(float2*)(sz + r * SZ_STRIDE + kw * 2) = Wg[i];
        }
        __syncthreads();
        if (tid < 256) {
            const float* w = sz + tid * SZ_STRIDE;
            float acc = 0.0f;
            #pragma unroll
            for (int k = 0; k < DIM; k++)
                acc = __fadd_rn(acc, __fmul_rn(w[k], w[k]));
            swsq[c * 256 + tid] = acc;   // exact sequential reference chain
        }
        __syncthreads();
    }

    // ===== Phase 2: wmax = max ||w_j|| (block tree in sred scratch) =====
    float wmax;
    {
        float* fs = (float*)sred;
        fs[tid] = sqrtf(swsq[tid]);
        __syncthreads();
        #pragma unroll
        for (int s = 256; s > 0; s >>= 1) {
            if (tid < s) fs[tid] = fmaxf(fs[tid], fs[tid + s]);
            __syncthreads();
        }
        wmax = fs[0] * 1.0001f;
        __syncthreads();
    }

    // ===== Phase 3: stage z (overwrites sz), fp16 W, init =====
    {
        const float2* zg = (const float2*)(z + (size_t)rowbase * DIM);
        for (int i = tid; i < ROWS_CTA * (DIM / 2); i += THREADS) {
            int r = i >> 5, c2 = i & 31;
            *(float2*)(sz + r * SZ_STRIDE + c2 * 2) = zg[i];
        }
        for (int i = tid; i < KCODES * (DIM / 2); i += THREADS) {
            int j = i >> 5, kw = i & 31;
            float2 g = ((const float2*)W)[i];
            __half2 h = __float22half2_rn(g);
            sW[j * SW_STRIDE + kw] = *(u32*)&h;
        }
        if (tid < ROWS_CTA) sbest[tid] = ~0ull;
        if (tid == 0) { sctl[0] = 0; sctl[1] = 0; }
        __syncthreads();
    }

    // ===== Phase 4: exact zz per row + rigorous width =====
    if (tid < ROWS_CTA) {
        const float* zr = sz + tid * SZ_STRIDE;
        float acc = 0.0f;
        #pragma unroll
        for (int k = 0; k < DIM; k++)
            acc = __fadd_rn(acc, __fmul_rn(zr[k], zr[k]));
        szz[tid] = acc;
        float znorm = sqrtf(acc) * 1.0001f;
        swid[tid] = 4.1e-3f * znorm * wmax + 1.1e-6f * znorm + 4.0e-5f;
    }
    __syncthreads();

    // ===== Phase 5: A fragments (rows m0, m0+8) fp16 from smem =====
    const int m0 = wid * 16 + gid;
    u32 A[4][4];
    #pragma unroll
    for (int kk = 0; kk < 4; kk++) {
        int kb = kk * 16;
        float2 p0 = *(float2*)(sz + m0 * SZ_STRIDE + kb + tig * 2);
        float2 p1 = *(float2*)(sz + (m0 + 8) * SZ_STRIDE + kb + tig * 2);
        float2 p2 = *(float2*)(sz + m0 * SZ_STRIDE + kb + 8 + tig * 2);
        float2 p3 = *(float2*)(sz + (m0 + 8) * SZ_STRIDE + kb + 8 + tig * 2);
        __half2 h;
        h = __float22half2_rn(p0); A[kk][0] = *(u32*)&h;
        h = __float22half2_rn(p1); A[kk][1] = *(u32*)&h;
        h = __float22half2_rn(p2); A[kk][2] = *(u32*)&h;
        h = __float22half2_rn(p3); A[kk][3] = *(u32*)&h;
    }

    // ===== Phase 6: single-pass filter, ballot-aggregated record =====
    {
        const float widA = swid[m0], widB = swid[m0 + 8];
        float rminA = 3.0e38f, rminB = 3.0e38f;

        #pragma unroll 1
        for (int n0 = 0; n0 < KCODES / 8; n0++) {
            const int j0 = n0 * 8;
            float c0 = 0.f, c1 = 0.f, c2 = 0.f, c3 = 0.f;
            const u32* wrow = sW + (j0 + gid) * SW_STRIDE + tig;
            #pragma unroll
            for (int kk = 0; kk < 4; kk++) {
                u32 b0 = wrow[kk * 8];
                u32 b1 = wrow[kk * 8 + 4];
                asm volatile(
                    "mma.sync.aligned.m16n8k16.row.col.f32.f16.f16.f32 "
                    "{%0,%1,%2,%3}, {%4,%5,%6,%7}, {%8,%9}, {%0,%1,%2,%3};"
                    : "+f"(c0), "+f"(c1), "+f"(c2), "+f"(c3)
                    : "r"(A[kk][0]), "r"(A[kk][1]), "r"(A[kk][2]), "r"(A[kk][3]),
                      "r"(b0), "r"(b1));
            }
            const int jc = j0 + tig * 2;
            float w0 = swsq[jc], w1 = swsq[jc + 1];
            float s0 = __fsub_rn(w0, __fmul_rn(2.0f, c0));
            float s1 = __fsub_rn(w1, __fmul_rn(2.0f, c1));
            float s2 = __fsub_rn(w0, __fmul_rn(2.0f, c2));
            float s3 = __fsub_rn(w1, __fmul_rn(2.0f, c3));

            // row-min across the 4 tig lanes (proven in R6)
            float mA = fminf(s0, s1);
            mA = fminf(mA, __shfl_xor_sync(FULL, mA, 1));
            mA = fminf(mA, __shfl_xor_sync(FULL, mA, 2));
            float mB = fminf(s2, s3);
            mB = fminf(mB, __shfl_xor_sync(FULL, mB, 1));
            mB = fminf(mB, __shfl_xor_sync(FULL, mB, 2));
            rminA = fminf(rminA, mA);
            rminB = fminf(rminB, mB);

            // running_min >= final_min -> threshold is a superset window
            const float tA = rminA + widA, tB = rminB + widB;
            bool k0 = (s0 <= tA), k1 = (s1 <= tA);
            bool k2 = (s2 <= tB), k3 = (s3 <= tB);
            u32 b0 = __ballot_sync(FULL, k0);
            u32 b1 = __ballot_sync(FULL, k1);
            u32 b2 = __ballot_sync(FULL, k2);
            u32 b3 = __ballot_sync(FULL, k3);
            if (b0 | b1 | b2 | b3) {
                int tot = __popc(b0) + __popc(b1) + __popc(b2) + __popc(b3);
                u32 base = 0;
                if (lane == 0) base = atomicAdd(&sctl[0], (u32)tot);
                base = __shfl_sync(FULL, base, 0);
                if (base + (u32)tot <= CAP) {
                    u32 lt = (1u << lane) - 1u;
                    int o1 = __popc(b0);
                    int o2 = o1 + __popc(b1);
                    int o3 = o2 + __popc(b2);
                    if (k0) scand[base + __popc(b0 & lt)]      = ((u32)m0 << 9) | (u32)jc;
                    if (k1) scand[base + o1 + __popc(b1 & lt)] = ((u32)m0 << 9) | (u32)(jc + 1);
                    if (k2) scand[base + o2 + __popc(b2 & lt)] = ((u32)(m0 + 8) << 9) | (u32)jc;
                    if (k3) scand[base + o3 + __popc(b3 & lt)] = ((u32)(m0 + 8) << 9) | (u32)(jc + 1);
                } else {
                    sctl[1] = 1;
                }
            }
        }
    }
    __syncthreads();

    // ===== Phase 7: deferred exact rescore (bitwise reference chain) =====
    if (sctl[1] == 0) {
        int n = min(sctl[0], (u32)CAP);
        for (int c = tid; c < n; c += THREADS) {
            u32 e = scand[c];
            int r = e >> 9, j = e & 511;
            const float* zr = sz + r * SZ_STRIDE;
            const float* wr = W + j * DIM;
            float acc = 0.0f;
            #pragma unroll
            for (int k = 0; k < DIM; k += 4) {
                float2 za = *(const float2*)(zr + k);
                float2 zb = *(const float2*)(zr + k + 2);
                float4 wv = *(const float4*)(wr + k);
                acc = __fmaf_rn(za.x, wv.x, acc);
                acc = __fmaf_rn(za.y, wv.y, acc);
                acc = __fmaf_rn(zb.x, wv.z, acc);
                acc = __fmaf_rn(zb.y, wv.w, acc);
            }
            float dist = __fsub_rn(__fadd_rn(szz[r], swsq[j]), __fmul_rn(2.0f, acc));
            atomicMin(&sbest[r], ((u64)fflip(dist) << 32) | (u32)j);
        }
    } else {
        // overflow fallback: warp-cooperative full exact scan (always correct)
        for (int r = wid; r < ROWS_CTA; r += THREADS / 32) {
            const float* zr = sz + r * SZ_STRIDE;
            u64 best = ~0ull;
            for (int j = lane; j < KCODES; j += 32) {
                const float* wr = W + j * DIM;
                float acc = 0.0f;
                #pragma unroll
                for (int k = 0; k < DIM; k += 4) {
                    float2 za = *(const float2*)(zr + k);
                    float2 zb = *(const float2*)(zr + k + 2);
                    float4 wv = *(const float4*)(wr + k);
                    acc = __fmaf_rn(za.x, wv.x, acc);
                    acc = __fmaf_rn(za.y, wv.y, acc);
                    acc = __fmaf_rn(zb.x, wv.z, acc);
                    acc = __fmaf_rn(zb.y, wv.w, acc);
                }
                float dist = __fsub_rn(__fadd_rn(szz[r], swsq[j]), __fmul_rn(2.0f, acc));
                best = min(best, ((u64)fflip(dist) << 32) | (u32)j);
            }
            #pragma unroll
            for (int off = 16; off > 0; off >>= 1)
                best = min(best, __shfl_xor_sync(FULL, best, off));
            if (lane == 0) atomicMin(&sbest[r], best);
        }
    }
    __syncthreads();

    // ===== Phase 8: epilogue (coalesced) + deterministic loss =====
    double dsum = 0.0;
    for (int i = tid; i < ROWS_CTA * DIM; i += THREADS) {
        int r = i >> 6, k = i & 63;
        int bj = (int)(sbest[r] & 0xFFFFFFFFull);
        float zv = sz[r * SZ_STRIDE + k];
        float wv = __ldg(W + bj * DIM + k);
        float st = __fadd_rn(zv, __fsub_rn(wv, zv));
        float df = __fsub_rn(zv, st);
        dsum += (double)__fmul_rn(df, df);
        out[(size_t)rowbase * DIM + i] = st;
    }
    if (tid < ROWS_CTA)
        out[NELEM_ZQ + rowbase + tid] = (float)(sbest[tid] & 0xFFFFFFFFull);

    sred[tid] = dsum;
    __syncthreads();
    #pragma unroll
    for (int s = THREADS / 2; s > 0; s >>= 1) {
        if (tid < s) sred[tid] += sred[tid + s];
        __syncthreads();
    }
    if (tid == 0) {
        // fixed-point (2^20) order-independent accumulation -> deterministic
        u64 part = (u64)__double2ll_rn(sred[0] * 1048576.0);
        atomicAdd(&g_acc, part);
        __threadfence();
        u32 t = atomicAdd(&g_done, 1u);
        if (t == GRIDM - 1) {                 // last CTA finalizes + resets
            u64 tot = atomicExch(&g_acc, 0ull);
            atomicExch(&g_done, 0u);
            double s = (double)tot * (1.0 / 1048576.0);
            int lp = NELEM_ZQ + NROWS;
            if (out_size > lp)
                out[lp] = (float)(0.25 * s / (double)NELEM_ZQ);
        }
    }
}

extern "C" void kernel_launch(void* const* d_in, const int* in_sizes, int n_in,
                              void* d_out, int out_size) {
    const float* z = (const float*)d_in[0];
    const float* W = (const float*)d_in[1];
    float* out = (float*)d_out;

    size_t smem = 6144
                + (size_t)ROWS_CTA * SZ_STRIDE * 4   // z / W-chunk temp
                + (size_t)KCODES * SW_STRIDE * 4     // W fp16
                + KCODES * 4                         // wsq
                + ROWS_CTA * 4 * 2                   // zz, width
                + (size_t)CAP * 4 + 16;              // candidates + ctl
    static bool attr_set = false;
    if (!attr_set) {
        cudaFuncSetAttribute(vq_all, cudaFuncAttributeMaxDynamicSharedMemorySize,
                             (int)smem);
        attr_set = true;
    }

    vq_all<<<GRIDM, THREADS, smem>>>(z, W, out, out_size);
}